// round 17
// baseline (speedup 1.0000x reference)
#include <cuda_runtime.h>
#include <cuda_fp16.h>
#include <stdint.h>

#define NN 100000
#define F  64
#define E_MAX 1700000
#define SCAN_T 1024
#define SCAN_B ((NN + SCAN_T - 1) / SCAN_T)   // 98 tiles

// ---- scratch (static __device__ arrays; no allocation allowed) ----
__device__ int      g_cnt[NN];          // in-degree (real edges only)
__device__ float    g_dis[NN];          // deg^{-1/2} (incl. self loop)
__device__ int      g_rowptr[NN + 1];
__device__ int      g_cursor[NN];
__device__ int      g_blocksum[SCAN_B];
__device__ int2     g_csr[E_MAX];       // {src, float_as_int(norm)} grouped by dst
__device__ uint32_t g_h16[NN * 32];     // H rows as 32 half2 per node (128B/row)
__device__ float    g_agg[NN * F];      // layer-1 aggregation result (fp32)
__device__ int      g_is64;             // edge_index dtype flag

// ---------------------------------------------------------------------------
// K0: detect edge_index dtype. For nonnegative int64 (LE), every odd 32-bit
// word is 0. For random int32 indices, essentially never.
__global__ void k_detect(const unsigned int* __restrict__ w) {
    if (threadIdx.x == 0 && blockIdx.x == 0) {
        int is64 = 1;
        #pragma unroll 1
        for (int i = 1; i < 128; i += 2)
            if (w[i] != 0u) { is64 = 0; break; }
        g_is64 = is64;
    }
}

__device__ __forceinline__ int load_idx(const void* ei, long long elem, int is64) {
    if (is64) return (int)((const long long*)ei)[elem];
    return ((const int*)ei)[elem];
}

// K1: in-degree histogram over real edges (dst row of edge_index [2,E])
__global__ void k_cnt_acc(const void* __restrict__ ei, int* cnt, int E) {
    int e = blockIdx.x * blockDim.x + threadIdx.x;
    if (e >= E) return;
    int d = load_idx(ei, (long long)E + e, g_is64);
    if ((unsigned)d < (unsigned)NN) atomicAdd(&cnt[d], 1);
}

// K2: dis = (cnt+1)^{-1/2}   (+1 self loop)
__global__ void k_dis(const int* __restrict__ cnt, float* dis, int n) {
    int i = blockIdx.x * blockDim.x + threadIdx.x;
    if (i < n) dis[i] = rsqrtf((float)cnt[i] + 1.0f);
}

// ---------------------------------------------------------------------------
// Multi-block exclusive scan of cnt -> rowptr/cursor. 3 phases.
__global__ void k_blocksum(const int* __restrict__ cnt, int* __restrict__ bsum, int n) {
    __shared__ int wsum[32];
    int i = blockIdx.x * SCAN_T + threadIdx.x;
    int v = (i < n) ? cnt[i] : 0;
    int lane = threadIdx.x & 31, warp = threadIdx.x >> 5;
    #pragma unroll
    for (int o = 16; o > 0; o >>= 1) v += __shfl_down_sync(0xffffffffu, v, o);
    if (lane == 0) wsum[warp] = v;
    __syncthreads();
    if (warp == 0) {
        int t = wsum[lane];
        #pragma unroll
        for (int o = 16; o > 0; o >>= 1) t += __shfl_down_sync(0xffffffffu, t, o);
        if (lane == 0) bsum[blockIdx.x] = t;
    }
}

__global__ void k_scan_base(int* __restrict__ bsum, int* __restrict__ rowptr, int nb, int n) {
    __shared__ int wsum[4];
    int tid = threadIdx.x;                       // 128 threads
    int v = (tid < nb) ? bsum[tid] : 0;
    int lane = tid & 31, warp = tid >> 5;
    int s = v;
    #pragma unroll
    for (int o = 1; o < 32; o <<= 1) {
        int t = __shfl_up_sync(0xffffffffu, s, o);
        if (lane >= o) s += t;
    }
    if (lane == 31) wsum[warp] = s;
    __syncthreads();
    int woff = 0;
    #pragma unroll
    for (int w = 0; w < 4; w++) if (w < warp) woff += wsum[w];
    int incl = s + woff;
    if (tid < nb) bsum[tid] = incl - v;          // exclusive tile offset
    if (tid == nb - 1) rowptr[n] = incl;         // grand total
}

__global__ void k_scan_tiles(const int* __restrict__ cnt, const int* __restrict__ bsum,
                             int* __restrict__ rowptr, int* __restrict__ cursor, int n) {
    __shared__ int wsum[32];
    int i = blockIdx.x * SCAN_T + threadIdx.x;
    int v = (i < n) ? cnt[i] : 0;
    int lane = threadIdx.x & 31, warp = threadIdx.x >> 5;
    int s = v;
    #pragma unroll
    for (int o = 1; o < 32; o <<= 1) {
        int t = __shfl_up_sync(0xffffffffu, s, o);
        if (lane >= o) s += t;
    }
    if (lane == 31) wsum[warp] = s;
    __syncthreads();
    if (warp == 0) {
        int ws = wsum[lane];
        #pragma unroll
        for (int o = 1; o < 32; o <<= 1) {
            int t = __shfl_up_sync(0xffffffffu, ws, o);
            if (lane >= o) ws += t;
        }
        wsum[lane] = ws;
    }
    __syncthreads();
    int excl = s - v + (warp > 0 ? wsum[warp - 1] : 0) + bsum[blockIdx.x];
    if (i < n) {
        rowptr[i] = excl;
        cursor[i] = excl;
    }
}

// K4: fill CSR — slot per edge via cursor atomic; store {src, norm}
__global__ void k_fill(const void* __restrict__ ei, const float* __restrict__ dis,
                       int* __restrict__ cursor, int2* __restrict__ csr, int E) {
    int e = blockIdx.x * blockDim.x + threadIdx.x;
    if (e >= E) return;
    int is64 = g_is64;
    int s = load_idx(ei, e, is64);
    int d = load_idx(ei, (long long)E + e, is64);
    if ((unsigned)s >= (unsigned)NN || (unsigned)d >= (unsigned)NN) return;
    float nm = dis[s] * dis[d];
    int slot = atomicAdd(&cursor[d], 1);
    csr[slot] = make_int2(s, __float_as_int(nm));
}

// ---------------------------------------------------------------------------
// GEMM: H16[n] = half2( act(X[n,64]) @ W[64,64] ). Warp-per-row, W in smem.
__global__ void k_gemm64(const float* __restrict__ X, const float* __restrict__ Wg,
                         uint32_t* __restrict__ H16, int n, int do_relu) {
    __shared__ __align__(16) float Ws[F * F];
    for (int i = threadIdx.x; i < F * F; i += blockDim.x) Ws[i] = Wg[i];
    __syncthreads();

    int warp = (blockIdx.x * blockDim.x + threadIdx.x) >> 5;
    int lane = threadIdx.x & 31;
    if (warp >= n) return;

    float2 xv = ((const float2*)(X + (size_t)warp * F))[lane];
    if (do_relu) { xv.x = fmaxf(xv.x, 0.0f); xv.y = fmaxf(xv.y, 0.0f); }

    float a0 = 0.0f, a1 = 0.0f;
#pragma unroll
    for (int k = 0; k < F; k++) {
        float xk = __shfl_sync(0xffffffffu, (k & 1) ? xv.y : xv.x, k >> 1);
        float2 w = ((const float2*)(Ws + k * F))[lane];
        a0 = fmaf(xk, w.x, a0);
        a1 = fmaf(xk, w.y, a1);
    }
    __half2 hh = __floats2half2_rn(a0, a1);
    H16[(size_t)warp * 32 + lane] = *(const uint32_t*)&hh;
}

// ---------------------------------------------------------------------------
// Gather-aggregate: warp per dst node. One coalesced 32-wide csr load per
// chunk; {src,norm} broadcast via shfl. H rows are fp16 (128B): half the L2
// bytes of fp32. fp32 accumulation. Unroll 8 for deep MLP.
__device__ __forceinline__ float2 h2f(uint32_t u) {
    return __half22float2(*(const __half2*)&u);
}

__global__ void __launch_bounds__(256) k_gather(
        const int* __restrict__ rowptr, const int2* __restrict__ csr,
        const uint32_t* __restrict__ H16, const float* __restrict__ dis,
        const float* __restrict__ b, float* __restrict__ Agg, int n) {
    int node = (blockIdx.x * blockDim.x + threadIdx.x) >> 5;
    int lane = threadIdx.x & 31;
    if (node >= n) return;

    int beg = rowptr[node];
    int end = rowptr[node + 1];

    float dd = dis[node];
    float sl = dd * dd;
    float2 hs = h2f(H16[(size_t)node * 32 + lane]);
    float2 bb = ((const float2*)b)[lane];
    float ax = fmaf(hs.x, sl, bb.x);
    float ay = fmaf(hs.y, sl, bb.y);

    #pragma unroll 1
    for (int base = beg; base < end; base += 32) {
        int m = end - base;
        if (m > 32) m = 32;
        int2 e = make_int2(0, 0);
        if (lane < m) e = __ldg(&csr[base + lane]);

        int k = 0;
        #pragma unroll 1
        for (; k + 7 < m; k += 8) {
            uint32_t u[8];
            float    nm[8];
            #pragma unroll
            for (int q = 0; q < 8; q++) {
                int   sq = __shfl_sync(0xffffffffu, e.x, k + q);
                nm[q]    = __int_as_float(__shfl_sync(0xffffffffu, e.y, k + q));
                u[q]     = __ldg(&H16[(size_t)sq * 32 + lane]);
            }
            #pragma unroll
            for (int q = 0; q < 8; q++) {
                float2 v = h2f(u[q]);
                ax = fmaf(v.x, nm[q], ax);
                ay = fmaf(v.y, nm[q], ay);
            }
        }
        #pragma unroll 1
        for (; k < m; k++) {
            int   sq = __shfl_sync(0xffffffffu, e.x, k);
            float nq = __int_as_float(__shfl_sync(0xffffffffu, e.y, k));
            float2 v = h2f(__ldg(&H16[(size_t)sq * 32 + lane]));
            ax = fmaf(v.x, nq, ax);
            ay = fmaf(v.y, nq, ay);
        }
    }
    ((float2*)(Agg + (size_t)node * F))[lane] = make_float2(ax, ay);
}

// ---------------------------------------------------------------------------
static inline int cdiv(int a, int b) { return (a + b - 1) / b; }

extern "C" void kernel_launch(void* const* d_in, const int* in_sizes, int n_in,
                              void* d_out, int out_size) {
    const float* x  = (const float*)d_in[0];
    const void*  ei = d_in[1];
    const float* W1 = (const float*)d_in[2];
    const float* b1 = (const float*)d_in[3];
    const float* W2 = (const float*)d_in[4];
    const float* b2 = (const float*)d_in[5];
    float*       out = (float*)d_out;

    const int N = in_sizes[0] / F;        // 100000
    const int E = in_sizes[1] / 2;        // 1600000
    const int NB = cdiv(N, SCAN_T);       // 98

    int *cnt, *rowptr, *cursor, *bsum;
    int2 *csr;
    float *dis, *agg;
    uint32_t *h16;
    cudaGetSymbolAddress((void**)&cnt,    g_cnt);
    cudaGetSymbolAddress((void**)&dis,    g_dis);
    cudaGetSymbolAddress((void**)&rowptr, g_rowptr);
    cudaGetSymbolAddress((void**)&cursor, g_cursor);
    cudaGetSymbolAddress((void**)&bsum,   g_blocksum);
    cudaGetSymbolAddress((void**)&csr,    g_csr);
    cudaGetSymbolAddress((void**)&h16,    g_h16);
    cudaGetSymbolAddress((void**)&agg,    g_agg);

    const int T = 256;

    // ---- preprocessing (once per call, reused by both layers) ----
    k_detect    <<<1, 32>>>((const unsigned int*)ei);
    cudaMemsetAsync(cnt, 0, (size_t)N * sizeof(int));
    k_cnt_acc   <<<cdiv(E, T), T>>>(ei, cnt, E);
    k_dis       <<<cdiv(N, T), T>>>(cnt, dis, N);
    k_blocksum  <<<NB, SCAN_T>>>(cnt, bsum, N);
    k_scan_base <<<1, 128>>>(bsum, rowptr, NB, N);
    k_scan_tiles<<<NB, SCAN_T>>>(cnt, bsum, rowptr, cursor, N);
    k_fill      <<<cdiv(E, T), T>>>(ei, dis, cursor, csr, E);

    // ---- layer 1 ----
    k_gemm64 <<<cdiv(N * 32, T), T>>>(x, W1, h16, N, 0);
    k_gather <<<cdiv(N * 32, T), T>>>(rowptr, csr, h16, dis, b1, agg, N);

    // ---- layer 2 ----
    k_gemm64 <<<cdiv(N * 32, T), T>>>(agg, W2, h16, N, 1);
    k_gather <<<cdiv(N * 32, T), T>>>(rowptr, csr, h16, dis, b2, out, N);
}